// round 12
// baseline (speedup 1.0000x reference)
#include <cuda_runtime.h>
#include <cuda_bf16.h>
#include <cstdint>

// Problem shapes (fixed by setup_inputs)
#define B_      4
#define L_      8192
#define BLOCK_  128
#define NB_     (L_ / BLOCK_)          // 64
#define V_      32000
#define D_      1024
#define NT_     (L_ + NB_)             // 8256 new_tokens per batch row

// Output layout (flattened tuple, row-major, float32):
//   [0,        B*NT)                new_tokens      (33024)
//   [OFF_CE,   OFF_CE + B*NB*D)     cat_emb         (262144)
//   [OFF_H,    OFF_H  + B*NB*V)     hist            (8192000)
#define OFF_CE  (B_ * NT_)                         // 33024
#define OFF_H   (OFF_CE + B_ * NB_ * D_)           // 295168

#define QUARTERS 4
#define QF32     (V_ / QUARTERS)                   // 8000 bins per quarter
#define QF4      (QF32 / 4)                        // 2000 float4 per quarter
#define NWORDS   (QF32 / 32)                       // 250 bitmap words
#define GRID_    (B_ * NB_ * QUARTERS)             // 1024 CTAs, one wave

__device__ __forceinline__ float4 bits_to_f4(uint32_t w, int i)
{
    const uint32_t bits = (w >> ((i & 7) << 2)) & 0xFu;
    float4 v;
    v.x = (bits & 1u) ? 1.0f : 0.0f;
    v.y = (bits & 2u) ? 1.0f : 0.0f;
    v.z = (bits & 4u) ? 1.0f : 0.0f;
    v.w = (bits & 8u) ? 1.0f : 0.0f;
    return v;
}

// Bitmap histogram, fully-unrolled two-phase drain:
//   phase A: gather 8 bitmap words -> registers (LDS burst)
//   phase B: 8 independent back-to-back STG.128 (front-batched store MLP)
// Side outputs: tokens stored pre-barrier; embed row PREFETCHED into a
// register before the final barrier, stored after the drain (so q==0 CTAs
// don't straggle the barrier and the DRAM gather latency hides under work).
__global__ __launch_bounds__(256)
void chunk_agg_bm2(const int* __restrict__ tokens,
                   const float* __restrict__ catW,
                   float* __restrict__ out)
{
    __shared__ uint32_t bm[NWORDS];      // 1000 B
    __shared__ int      ov_tok[BLOCK_];  // duplicate rel-bins (exactness)
    __shared__ int      ov_cnt;
    __shared__ int      s_t0;

    const int bid = blockIdx.x;
    const int q   = bid & (QUARTERS - 1);
    const int bj  = bid >> 2;            // 0..255
    const int b   = bj >> 6;
    const int j   = bj & 63;
    const int tid = threadIdx.x;

    const int* __restrict__ blk = tokens + b * L_ + j * BLOCK_;

    // early token load (overlaps with bitmap zeroing)
    const int mytok = (tid < BLOCK_) ? blk[tid] : 0;

    // ---- zero bitmap + counters
    if (tid < NWORDS) bm[tid] = 0u;
    if (tid == 0) { ov_cnt = 0; s_t0 = mytok; }

    // ---- new_tokens (fire-and-forget scalar stores)
    if (q == 0) {
        if (tid < BLOCK_)
            out[b * NT_ + NB_ + j * BLOCK_ + tid] = (float)mytok;
        if (tid == 0)
            out[b * NT_ + j] = (float)mytok;
    }

    __syncthreads();

    // ---- presence bits + exact duplicate list
    if (tid < BLOCK_) {
        const int lo = q * QF32;
        if (mytok >= lo && mytok < lo + QF32) {
            const int rel = mytok - lo;
            const uint32_t mask = 1u << (rel & 31);
            const uint32_t old  = atomicOr(&bm[rel >> 5], mask);
            if (old & mask) {
                const int k = atomicAdd(&ov_cnt, 1);
                ov_tok[k] = rel;
            }
        }
    }

    // ---- embed-row PREFETCH (q==0): issue LDG now, consume after drain
    float4 emb = make_float4(0.f, 0.f, 0.f, 0.f);
    if (q == 0) {
        const int t0 = s_t0;   // written by tid 0 before the first barrier
        emb = reinterpret_cast<const float4*>(catW + (size_t)t0 * D_)[tid];
    }

    __syncthreads();

    // ---- drain: batched gather then batched stores
    float4* __restrict__ h4 =
        reinterpret_cast<float4*>(out + OFF_H + (size_t)bj * V_ + q * QF32);
    const int novf = ov_cnt;

    if (novf == 0) {
        uint32_t w[8];
        #pragma unroll
        for (int k = 0; k < 8; ++k) {
            const int i = tid + (k << 8);
            if (k < 7 || i < QF4) w[k] = bm[i >> 3];
        }
        #pragma unroll
        for (int k = 0; k < 8; ++k) {
            const int i = tid + (k << 8);
            if (k < 7 || i < QF4) h4[i] = bits_to_f4(w[k], i);
        }
    } else {
        #pragma unroll
        for (int k = 0; k < 8; ++k) {
            const int i = tid + (k << 8);
            if (k < 7 || i < QF4) {
                float4 v = bits_to_f4(bm[i >> 3], i);
                for (int e = 0; e < novf; ++e) {
                    const int rel = ov_tok[e];
                    if ((rel >> 2) == i) {
                        switch (rel & 3) {
                            case 0: v.x += 1.0f; break;
                            case 1: v.y += 1.0f; break;
                            case 2: v.z += 1.0f; break;
                            default: v.w += 1.0f; break;
                        }
                    }
                }
                h4[i] = v;
            }
        }
    }

    // ---- embed-row store (prefetched above; latency long hidden)
    if (q == 0)
        reinterpret_cast<float4*>(out + OFF_CE + bj * D_)[tid] = emb;
}

extern "C" void kernel_launch(void* const* d_in, const int* in_sizes, int n_in,
                              void* d_out, int out_size)
{
    const int*   tokens = (const int*)  d_in[0];   // [4, 8192] int32
    const float* catW   = (const float*)d_in[1];   // [32000, 1024] f32
    // d_in[2] (num_embed_W) is a dead lookup in the reference — unused.
    float* out = (float*)d_out;

    chunk_agg_bm2<<<GRID_, 256>>>(tokens, catW, out);
}

// round 13
// speedup vs baseline: 1.0269x; 1.0269x over previous
#include <cuda_runtime.h>
#include <cuda_bf16.h>
#include <cstdint>

// Problem shapes (fixed by setup_inputs)
#define B_      4
#define L_      8192
#define BLOCK_  128
#define NB_     (L_ / BLOCK_)          // 64
#define V_      32000
#define D_      1024
#define NT_     (L_ + NB_)             // 8256 new_tokens per batch row

// Output layout (flattened tuple, row-major, float32):
//   [0,        B*NT)                new_tokens      (33024)
//   [OFF_CE,   OFF_CE + B*NB*D)     cat_emb         (262144)
//   [OFF_H,    OFF_H  + B*NB*V)     hist            (8192000)
#define OFF_CE  (B_ * NT_)                         // 33024
#define OFF_H   (OFF_CE + B_ * NB_ * D_)           // 295168

#define QUARTERS 4
#define QF32     (V_ / QUARTERS)                   // 8000 bins per quarter
#define NCHUNK   (QF32 / 8)                        // 1000 v8 (32B) chunks
#define NWORDS   (QF32 / 32)                       // 250 bitmap words
#define GRID_    (B_ * NB_ * QUARTERS)             // 1024 CTAs, one wave

// 256-bit store: one STG.256 per 8 floats (sm_100+).
__device__ __forceinline__ void stg_v8(float* p, const float* v)
{
    asm volatile(
        "st.global.v8.f32 [%0], {%1,%2,%3,%4,%5,%6,%7,%8};"
        :: "l"(p),
           "f"(v[0]), "f"(v[1]), "f"(v[2]), "f"(v[3]),
           "f"(v[4]), "f"(v[5]), "f"(v[6]), "f"(v[7])
        : "memory");
}

// Bitmap histogram + 256-bit store drain.
// CTA (bj, q):
//   1. zero 250-word bitmap
//   2. atomicOr presence bits (exact duplicates -> overflow list)
//   3. drain: one byte of bitmap -> 8 floats -> st.global.v8 (4 per thread,
//      interleaved schedule — the front-batched variant regressed)
//   4. (q==0) new_tokens early; embed row prefetched pre-barrier,
//      stored post-drain.
__global__ __launch_bounds__(256)
void chunk_agg_v8(const int* __restrict__ tokens,
                  const float* __restrict__ catW,
                  float* __restrict__ out)
{
    __shared__ uint32_t bm[NWORDS];      // 1000 B
    __shared__ int      ov_tok[BLOCK_];  // duplicate rel-bins
    __shared__ int      ov_cnt;
    __shared__ int      s_t0;

    const int bid = blockIdx.x;
    const int q   = bid & (QUARTERS - 1);
    const int bj  = bid >> 2;            // 0..255
    const int b   = bj >> 6;
    const int j   = bj & 63;
    const int tid = threadIdx.x;

    const int* __restrict__ blk = tokens + b * L_ + j * BLOCK_;

    // early token load (overlaps bitmap zeroing)
    const int mytok = (tid < BLOCK_) ? blk[tid] : 0;

    // ---- 1) zero bitmap + counters
    if (tid < NWORDS) bm[tid] = 0u;
    if (tid == 0) { ov_cnt = 0; s_t0 = mytok; }

    // ---- new_tokens (fire-and-forget)
    if (q == 0) {
        if (tid < BLOCK_)
            out[b * NT_ + NB_ + j * BLOCK_ + tid] = (float)mytok;
        if (tid == 0)
            out[b * NT_ + j] = (float)mytok;
    }

    __syncthreads();

    // ---- 2) presence bits + exact duplicate list
    if (tid < BLOCK_) {
        const int lo = q * QF32;
        if (mytok >= lo && mytok < lo + QF32) {
            const int rel = mytok - lo;
            const uint32_t mask = 1u << (rel & 31);
            const uint32_t old  = atomicOr(&bm[rel >> 5], mask);
            if (old & mask) {
                const int k = atomicAdd(&ov_cnt, 1);
                ov_tok[k] = rel;
            }
        }
    }

    // ---- embed-row prefetch (q==0): LDG issued here, consumed after drain
    float4 emb = make_float4(0.f, 0.f, 0.f, 0.f);
    if (q == 0)
        emb = reinterpret_cast<const float4*>(catW + (size_t)s_t0 * D_)[tid];

    __syncthreads();

    // ---- 3) drain: 1000 x 32B chunks, 4 per thread, STG.256 each
    float* __restrict__ histq = out + OFF_H + (size_t)bj * V_ + q * QF32;
    const int novf = ov_cnt;

    if (novf == 0) {
        #pragma unroll
        for (int k = 0; k < 4; ++k) {
            const int i = tid + (k << 8);        // chunk index
            if (i < NCHUNK) {
                const uint32_t byte = (bm[i >> 2] >> ((i & 3) << 3)) & 0xFFu;
                float v[8];
                #pragma unroll
                for (int e = 0; e < 8; ++e)
                    v[e] = (byte >> e) & 1u ? 1.0f : 0.0f;
                stg_v8(histq + i * 8, v);
            }
        }
    } else {
        #pragma unroll
        for (int k = 0; k < 4; ++k) {
            const int i = tid + (k << 8);
            if (i < NCHUNK) {
                const uint32_t byte = (bm[i >> 2] >> ((i & 3) << 3)) & 0xFFu;
                float v[8];
                #pragma unroll
                for (int e = 0; e < 8; ++e)
                    v[e] = (byte >> e) & 1u ? 1.0f : 0.0f;
                for (int e2 = 0; e2 < novf; ++e2) {
                    const int rel = ov_tok[e2];
                    if ((rel >> 3) == i)
                        v[rel & 7] += 1.0f;
                }
                stg_v8(histq + i * 8, v);
            }
        }
    }

    // ---- embed-row store (prefetched; latency hidden under the drain)
    if (q == 0)
        reinterpret_cast<float4*>(out + OFF_CE + bj * D_)[tid] = emb;
}

extern "C" void kernel_launch(void* const* d_in, const int* in_sizes, int n_in,
                              void* d_out, int out_size)
{
    const int*   tokens = (const int*)  d_in[0];   // [4, 8192] int32
    const float* catW   = (const float*)d_in[1];   // [32000, 1024] f32
    // d_in[2] (num_embed_W) is a dead lookup in the reference — unused.
    float* out = (float*)d_out;

    chunk_agg_v8<<<GRID_, 256>>>(tokens, catW, out);
}